// round 12
// baseline (speedup 1.0000x reference)
#include <cuda_runtime.h>

#define B_ 256
#define S_ 512
#define V_ 32000
#define D_ 100
#define H_ 75
#define HP_ 76   // g_embp row stride
#define KP_ 80   // padded state stride (76 used, 16B-aligned)
#define L_ 128
#define NTHR 160 // 5 warps: AB=0..2 (75 lanes), C=3..4 (64 lanes x 2 outputs)

// Precomputed emb @ W1^T + b1, stride 76. 32000*76*4 = 9.73 MB (L2-resident).
__device__ float g_embp[V_ * HP_];

// ---------------------------------------------------------------------------
// Kernel 1: embp[v][j] = sum_d emb[v][d] * W1[j][d] + b1[j]
// ---------------------------------------------------------------------------
__global__ __launch_bounds__(256) void embp_kernel(const float* __restrict__ emb,
                                                   const float* __restrict__ W1,
                                                   const float* __restrict__ b1) {
    __shared__ float w1s[H_ * D_];
    __shared__ float es[64 * D_];
    const int r0 = blockIdx.x * 64;

    for (int idx = threadIdx.x; idx < H_ * D_; idx += 256) w1s[idx] = W1[idx];
    for (int idx = threadIdx.x; idx < 64 * D_; idx += 256) es[idx] = emb[r0 * D_ + idx];
    __syncthreads();

    for (int o = threadIdx.x; o < 64 * H_; o += 256) {
        const int rr = o / H_;
        const int j  = o - rr * H_;
        const float* ep = es + rr * D_;
        const float* wp = w1s + j * D_;
        float4 a = {0.f, 0.f, 0.f, 0.f};
#pragma unroll
        for (int k = 0; k < D_ / 4; ++k) {
            float4 ev = *(const float4*)(ep + 4 * k);
            float4 wv = *(const float4*)(wp + 4 * k);
            a.x += ev.x * wv.x; a.y += ev.y * wv.y;
            a.z += ev.z * wv.z; a.w += ev.w * wv.w;
        }
        g_embp[(r0 + rr) * HP_ + j] = a.x + a.y + a.z + a.w + b1[j];
    }
}

// ---------------------------------------------------------------------------
// Packed fp32x2 helpers (sm_103a)
// ---------------------------------------------------------------------------
__device__ __forceinline__ unsigned long long pack2(float lo, float hi) {
    unsigned long long d;
    asm("mov.b64 %0, {%1, %2};" : "=l"(d) : "f"(lo), "f"(hi));
    return d;
}
__device__ __forceinline__ void fma2(unsigned long long& d, unsigned long long a,
                                     unsigned long long b) {
    asm("fma.rn.f32x2 %0, %1, %2, %0;" : "+l"(d) : "l"(a), "l"(b));
}
__device__ __forceinline__ float hsum2(unsigned long long a, unsigned long long b) {
    unsigned long long s;
    asm("add.rn.f32x2 %0, %1, %2;" : "=l"(s) : "l"(a), "l"(b));
    float lo, hi;
    asm("mov.b64 {%0, %1}, %2;" : "=f"(lo), "=f"(hi) : "l"(s));
    return lo + hi;
}
__device__ __forceinline__ float sigm(float z) {
    return __fdividef(1.0f, 1.0f + __expf(-z));
}

// Two full 76-float dots sharing ONE smem vector load (19 broadcast LDS.128):
// z0 = v . wa, z1 = v . wb. 2 packed accumulators per dot (chain depth ~10).
__device__ __forceinline__ float2 dot76x2(const float* __restrict__ v,
                                          const unsigned long long* __restrict__ wa,
                                          const unsigned long long* __restrict__ wb) {
    const ulonglong2* p = (const ulonglong2*)v;
    unsigned long long a0 = 0ull, a1 = 0ull, b0 = 0ull, b1 = 0ull;
#pragma unroll
    for (int i = 0; i < 19; ++i) {
        const ulonglong2 hv = p[i];               // broadcast LDS.128, feeds BOTH dots
        fma2(a0, wa[2 * i],     hv.x);
        fma2(b0, wb[2 * i],     hv.x);
        fma2(a1, wa[2 * i + 1], hv.y);
        fma2(b1, wb[2 * i + 1], hv.y);
    }
    return make_float2(hsum2(a0, a1), hsum2(b0, b1));
}

// ---------------------------------------------------------------------------
// Kernel 2: persistent-weight recurrence, one batch row per block, 256 blocks,
// 2 blocks/SM. Each state-vector smem load is shared by two dot products:
//   warps 0-2 (lane j<75): A h_tt = sigm(W2.h + xp + b2)  AND  B o_{tt-1} =
//                          sigm(Wo.h + bo)   (same h vector, one load)
//   warps 3-4 (lane c<64): C out_{tt-2}[2c,2c+1] = Wfc[2c..].o_{tt-2} + bfc
// Double-buffered h/o; ONE __syncthreads per step.
// ---------------------------------------------------------------------------
__global__ __launch_bounds__(NTHR, 2) void rnn_kernel(
    const int*   __restrict__ X,
    const float* __restrict__ W2, const float* __restrict__ b2,
    const float* __restrict__ Wo, const float* __restrict__ bo,
    const float* __restrict__ Wfc, const float* __restrict__ bfc,
    float* __restrict__ out)
{
    __shared__ __align__(16) float hs[2][KP_];   // [buf][k]
    __shared__ __align__(16) float os[2][KP_];
    __shared__ int toks[S_];

    const int tid = threadIdx.x;
    const int row = blockIdx.x;                  // one batch row per block

    const bool isAB = tid < 96;                  // warps 0-2
    const int  j    = isAB ? (tid < H_ ? tid : 0) : 0;     // AB output (clamped)
    const bool vAB  = isAB && (tid < H_);
    const int  c    = isAB ? 0 : (tid - 96);     // C pair index 0..63

    // ---- init state + tokens ----
    for (int i = tid; i < 2 * KP_; i += NTHR) {
        ((float*)hs)[i] = 0.f; ((float*)os)[i] = 0.f;
    }
    for (int i = tid; i < S_; i += NTHR) toks[i] = X[row * S_ + i];

    // ---- weights: two rows per thread, packed k-pairs (2 x 38 u64) ----
    const float* r0p = isAB ? (W2 + j * H_) : (Wfc + (2 * c) * H_);
    const float* r1p = isAB ? (Wo + j * H_) : (Wfc + (2 * c + 1) * H_);
    unsigned long long wa[38], wb[38];
#pragma unroll
    for (int cc = 0; cc < 38; ++cc) {
        const int k = 2 * cc;
        float lo = 0.f, hi = 0.f;
        if (k     < H_) { lo = r0p[k]; }
        if (k + 1 < H_) { hi = r0p[k + 1]; }
        wa[cc] = pack2(lo, hi);
        lo = 0.f; hi = 0.f;
        if (k     < H_) { lo = r1p[k]; }
        if (k + 1 < H_) { hi = r1p[k + 1]; }
        wb[cc] = pack2(lo, hi);
    }
    float bi0, bi1;
    if (isAB) { bi0 = vAB ? b2[j] : 0.f; bi1 = vAB ? bo[j] : 0.f; }
    else      { bi0 = bfc[2 * c];        bi1 = bfc[2 * c + 1]; }
    float* outp = out + ((size_t)row * S_) * L_ + 2 * c;   // C store base (float2)

    __syncthreads();

    float xpv = 0.f;
    if (vAB) xpv = g_embp[(size_t)toks[0] * HP_ + j];

    for (int tt = 0; tt < S_ + 2; ++tt) {
        const int pb = tt & 1;

        if (isAB) {
            if (tt <= S_) {
                float xn = 0.f;
                if (tt + 1 < S_)                  // prefetch next xp (overlaps dots)
                    xn = g_embp[(size_t)toks[tt + 1 < S_ ? tt + 1 : 0] * HP_ + j];
                const float2 z = dot76x2(hs[pb], wa, wb);   // one load, two dots
                if (vAB) {
                    if (tt < S_)  hs[pb ^ 1][j] = sigm(z.x + xpv + bi0);  // h_tt
                    if (tt >= 1)  os[pb][j]     = sigm(z.y + bi1);        // o_{tt-1}
                }
                xpv = xn;
            }
        } else {
            if (tt >= 2) {
                const float2 z = dot76x2(os[pb ^ 1], wa, wb);
                *(float2*)(outp + (size_t)(tt - 2) * L_) =
                    make_float2(z.x + bi0, z.y + bi1);       // out_{tt-2}
            }
        }
        __syncthreads();   // writes target buffers nobody reads this step
    }
}

// ---------------------------------------------------------------------------
extern "C" void kernel_launch(void* const* d_in, const int* in_sizes, int n_in,
                              void* d_out, int out_size) {
    const int*   X   = (const int*)d_in[0];
    const float* emb = (const float*)d_in[1];
    const float* W1  = (const float*)d_in[2];
    const float* b1  = (const float*)d_in[3];
    const float* W2  = (const float*)d_in[4];
    const float* b2  = (const float*)d_in[5];
    const float* Wo  = (const float*)d_in[6];
    const float* bo  = (const float*)d_in[7];
    const float* Wfc = (const float*)d_in[8];
    const float* bfc = (const float*)d_in[9];
    float* out = (float*)d_out;

    embp_kernel<<<V_ / 64, 256>>>(emb, W1, b1);
    rnn_kernel<<<B_, NTHR>>>(X, W2, b2, Wo, bo, Wfc, bfc, out);
}

// round 14
// speedup vs baseline: 1.7096x; 1.7096x over previous
#include <cuda_runtime.h>

#define B_ 256
#define S_ 512
#define V_ 32000
#define D_ 100
#define H_ 75
#define HP_ 76   // g_embp row stride
#define KP_ 80   // padded state stride (76 used; halves of 40 are 16B-aligned)
#define L_ 128
#define NTHR 320 // 10 warps: A=0..2, B=3..5, C=6..9 (one batch row per block)

// Precomputed emb @ W1^T + b1, stride 76. 32000*76*4 = 9.73 MB (L2-resident).
__device__ float g_embp[V_ * HP_];

// ---------------------------------------------------------------------------
// Kernel 1: embp[v][j] = sum_d emb[v][d] * W1[j][d] + b1[j]
// ---------------------------------------------------------------------------
__global__ __launch_bounds__(256) void embp_kernel(const float* __restrict__ emb,
                                                   const float* __restrict__ W1,
                                                   const float* __restrict__ b1) {
    __shared__ float w1s[H_ * D_];
    __shared__ float es[64 * D_];
    const int r0 = blockIdx.x * 64;

    for (int idx = threadIdx.x; idx < H_ * D_; idx += 256) w1s[idx] = W1[idx];
    for (int idx = threadIdx.x; idx < 64 * D_; idx += 256) es[idx] = emb[r0 * D_ + idx];
    __syncthreads();

    for (int o = threadIdx.x; o < 64 * H_; o += 256) {
        const int rr = o / H_;
        const int j  = o - rr * H_;
        const float* ep = es + rr * D_;
        const float* wp = w1s + j * D_;
        float4 a = {0.f, 0.f, 0.f, 0.f};
#pragma unroll
        for (int k = 0; k < D_ / 4; ++k) {
            float4 ev = *(const float4*)(ep + 4 * k);
            float4 wv = *(const float4*)(wp + 4 * k);
            a.x += ev.x * wv.x; a.y += ev.y * wv.y;
            a.z += ev.z * wv.z; a.w += ev.w * wv.w;
        }
        g_embp[(r0 + rr) * HP_ + j] = a.x + a.y + a.z + a.w + b1[j];
    }
}

// ---------------------------------------------------------------------------
// Packed fp32x2 helpers (sm_103a)
// ---------------------------------------------------------------------------
__device__ __forceinline__ unsigned long long pack2(float lo, float hi) {
    unsigned long long d;
    asm("mov.b64 %0, {%1, %2};" : "=l"(d) : "f"(lo), "f"(hi));
    return d;
}
__device__ __forceinline__ void fma2(unsigned long long& d, unsigned long long a,
                                     unsigned long long b) {
    asm("fma.rn.f32x2 %0, %1, %2, %0;" : "+l"(d) : "l"(a), "l"(b));
}
__device__ __forceinline__ float hsum2(unsigned long long a, unsigned long long b) {
    unsigned long long s;
    asm("add.rn.f32x2 %0, %1, %2;" : "=l"(s) : "l"(a), "l"(b));
    float lo, hi;
    asm("mov.b64 {%0, %1}, %2;" : "=f"(lo), "=f"(hi) : "l"(s));
    return lo + hi;
}
__device__ __forceinline__ float sigm(float z) {
    return __fdividef(1.0f, 1.0f + __expf(-z));
}

// Half-vector (40 floats at k0) dotted against two half-rows (wa, wb):
// 10 broadcast LDS.128, 20+20 fma2, 4 accumulators. Returns both partials.
__device__ __forceinline__ float2 halfdot2(const float* __restrict__ v, int k0,
                                           const unsigned long long* __restrict__ wa,
                                           const unsigned long long* __restrict__ wb) {
    const ulonglong2* p = (const ulonglong2*)(v + k0);
    unsigned long long a0 = 0ull, a1 = 0ull, b0 = 0ull, b1 = 0ull;
#pragma unroll
    for (int i = 0; i < 10; ++i) {
        const ulonglong2 hv = p[i];               // broadcast LDS.128 (half vector)
        fma2(a0, wa[2 * i],     hv.x);
        fma2(b0, wb[2 * i],     hv.x);
        fma2(a1, wa[2 * i + 1], hv.y);
        fma2(b1, wb[2 * i + 1], hv.y);
    }
    return make_float2(hsum2(a0, a1), hsum2(b0, b1));
}

// ---------------------------------------------------------------------------
// Kernel 2: persistent-weight recurrence, one batch row per block, 256 blocks,
// 2 blocks/SM (20 warps). k-split lane pairs: lanes (2m, 2m+1) each hold the
// q-th k-half (40 floats) of BOTH output rows (2m, 2m+1); each loads only its
// half of the state vector, computes two half-dots, and one shfl_xor(1)
// completes both outputs. Per-thread: 10 LDS.128 (was 19), 40 u64 weight regs.
//   warps 0-2 (j=tid<96):    A  h_tt     = sigm(W2 . h_{tt-1} + xp_tt + b2)
//   warps 3-5 (j=tid-96):    B  o_{tt-1} = sigm(Wo . h_{tt-1} + bo)
//   warps 6-9 (j=tid-192):   C  out_{tt-2}[j] = Wfc[j] . o_{tt-2} + bfc[j]
// Double-buffered h/o; ONE __syncthreads per step.
// ---------------------------------------------------------------------------
__global__ __launch_bounds__(NTHR, 2) void rnn_kernel(
    const int*   __restrict__ X,
    const float* __restrict__ W2, const float* __restrict__ b2,
    const float* __restrict__ Wo, const float* __restrict__ bo,
    const float* __restrict__ Wfc, const float* __restrict__ bfc,
    float* __restrict__ out)
{
    __shared__ __align__(16) float hs[2][KP_];   // [buf][k], pads [75..79]=0
    __shared__ __align__(16) float os[2][KP_];
    __shared__ int toks[S_];

    const int tid = threadIdx.x;
    const int row = blockIdx.x;                  // one batch row per block

    const bool isA = tid < 96;
    const bool isB = (tid >= 96) && (tid < 192);
    const int  j   = isA ? tid : (isB ? tid - 96 : tid - 192);   // own output
    const int  q   = j & 1;                      // k-half owned by this lane
    const int  k0  = q * 40;
    const int  j0  = j & ~1;                     // pair's even output row
    const int  j1  = j0 + 1;                     // pair's odd output row
    const int  nrows = (isA || isB) ? H_ : L_;
    const bool vst = j < nrows;                  // may store own output

    // ---- init state + tokens ----
    for (int i = tid; i < 2 * KP_; i += NTHR) {
        ((float*)hs)[i] = 0.f; ((float*)os)[i] = 0.f;
    }
    for (int i = tid; i < S_; i += NTHR) toks[i] = X[row * S_ + i];

    // ---- weights: the q-th k-half of rows j0 and j1 (20 u64 each) ----
    const float* Wbase = isA ? W2 : (isB ? Wo : Wfc);
    unsigned long long wa[20], wb[20];
#pragma unroll
    for (int c = 0; c < 20; ++c) {
        const int k = k0 + 2 * c;
        float lo = 0.f, hi = 0.f;
        if (j0 < nrows) {
            if (k     < H_) lo = Wbase[j0 * H_ + k];
            if (k + 1 < H_) hi = Wbase[j0 * H_ + k + 1];
        }
        wa[c] = pack2(lo, hi);
        lo = 0.f; hi = 0.f;
        if (j1 < nrows) {
            if (k     < H_) lo = Wbase[j1 * H_ + k];
            if (k + 1 < H_) hi = Wbase[j1 * H_ + k + 1];
        }
        wb[c] = pack2(lo, hi);
    }
    float br = 0.f;
    if (vst) br = isA ? b2[j] : (isB ? bo[j] : bfc[j]);
    float* outp = out + ((size_t)row * S_) * L_ + j;   // used by C

    __syncthreads();

    float xpv = 0.f;
    if (isA && vst) xpv = g_embp[(size_t)toks[0] * HP_ + j];

    for (int tt = 0; tt < S_ + 2; ++tt) {
        const int pb = tt & 1;

        if (isA || isB) {                          // warps 0-5, uniform branch
            if (tt <= S_) {
                float xn = 0.f;
                if (isA && vst && (tt + 1 < S_))   // prefetch next xp (overlaps dot)
                    xn = g_embp[(size_t)toks[tt + 1] * HP_ + j];
                const float2 pd = halfdot2(hs[pb], k0, wa, wb);
                // exchange the partial belonging to the partner's output
                const float send = q ? pd.x : pd.y;
                const float recv = __shfl_xor_sync(0xffffffffu, send, 1);
                const float z = (q ? pd.y : pd.x) + recv + br;
                if (isA) {
                    if (vst && tt < S_) hs[pb ^ 1][j] = sigm(z + xpv);  // h_tt
                    xpv = xn;
                } else {
                    if (vst && tt >= 1) os[pb][j] = sigm(z);           // o_{tt-1}
                }
            }
        } else {                                   // warps 6-9 (C), uniform branch
            if (tt >= 2) {
                const float2 pd = halfdot2(os[pb ^ 1], k0, wa, wb);
                const float send = q ? pd.x : pd.y;
                const float recv = __shfl_xor_sync(0xffffffffu, send, 1);
                const float z = (q ? pd.y : pd.x) + recv + br;
                outp[(size_t)(tt - 2) * L_] = z;   // out_{tt-2}
            }
        }
        __syncthreads();   // writes target buffers nobody reads this step
    }
}

// ---------------------------------------------------------------------------
extern "C" void kernel_launch(void* const* d_in, const int* in_sizes, int n_in,
                              void* d_out, int out_size) {
    const int*   X   = (const int*)d_in[0];
    const float* emb = (const float*)d_in[1];
    const float* W1  = (const float*)d_in[2];
    const float* b1  = (const float*)d_in[3];
    const float* W2  = (const float*)d_in[4];
    const float* b2  = (const float*)d_in[5];
    const float* Wo  = (const float*)d_in[6];
    const float* bo  = (const float*)d_in[7];
    const float* Wfc = (const float*)d_in[8];
    const float* bfc = (const float*)d_in[9];
    float* out = (float*)d_out;

    embp_kernel<<<V_ / 64, 256>>>(emb, W1, b1);
    rnn_kernel<<<B_, NTHR>>>(X, W2, b2, Wo, bo, Wfc, bfc, out);
}

// round 16
// speedup vs baseline: 1.7205x; 1.0064x over previous
#include <cuda_runtime.h>

#define B_ 256
#define S_ 512
#define V_ 32000
#define D_ 100
#define H_ 75
#define HP_ 76    // g_embp row stride
#define KP_ 80    // padded state stride (76 used, 16B-aligned)
#define L_ 128
#define NTHR 320  // 10 warps: A=0..2, B=3..5, C=6..9 (one batch row per block)
#define RING 8
#define EPOCHS (S_ / 4 + 2)   // 130: A epochs 0..127, B lags 4, C lags 8

// Precomputed emb @ W1^T + b1, stride 76. 32000*76*4 = 9.73 MB (L2-resident).
__device__ float g_embp[V_ * HP_];

// ---------------------------------------------------------------------------
// Kernel 1: embp[v][j] = sum_d emb[v][d] * W1[j][d] + b1[j]
// ---------------------------------------------------------------------------
__global__ __launch_bounds__(256) void embp_kernel(const float* __restrict__ emb,
                                                   const float* __restrict__ W1,
                                                   const float* __restrict__ b1) {
    __shared__ float w1s[H_ * D_];
    __shared__ float es[64 * D_];
    const int r0 = blockIdx.x * 64;

    for (int idx = threadIdx.x; idx < H_ * D_; idx += 256) w1s[idx] = W1[idx];
    for (int idx = threadIdx.x; idx < 64 * D_; idx += 256) es[idx] = emb[r0 * D_ + idx];
    __syncthreads();

    for (int o = threadIdx.x; o < 64 * H_; o += 256) {
        const int rr = o / H_;
        const int j  = o - rr * H_;
        const float* ep = es + rr * D_;
        const float* wp = w1s + j * D_;
        float4 a = {0.f, 0.f, 0.f, 0.f};
#pragma unroll
        for (int k = 0; k < D_ / 4; ++k) {
            float4 ev = *(const float4*)(ep + 4 * k);
            float4 wv = *(const float4*)(wp + 4 * k);
            a.x += ev.x * wv.x; a.y += ev.y * wv.y;
            a.z += ev.z * wv.z; a.w += ev.w * wv.w;
        }
        g_embp[(r0 + rr) * HP_ + j] = a.x + a.y + a.z + a.w + b1[j];
    }
}

// ---------------------------------------------------------------------------
// Packed fp32x2 helpers (sm_103a)
// ---------------------------------------------------------------------------
__device__ __forceinline__ unsigned long long pack2(float lo, float hi) {
    unsigned long long d;
    asm("mov.b64 %0, {%1, %2};" : "=l"(d) : "f"(lo), "f"(hi));
    return d;
}
__device__ __forceinline__ void fma2(unsigned long long& d, unsigned long long a,
                                     unsigned long long b) {
    asm("fma.rn.f32x2 %0, %1, %2, %0;" : "+l"(d) : "l"(a), "l"(b));
}
__device__ __forceinline__ float hsum4(unsigned long long a, unsigned long long b,
                                       unsigned long long c, unsigned long long d) {
    unsigned long long s0, s1;
    asm("add.rn.f32x2 %0, %1, %2;" : "=l"(s0) : "l"(a), "l"(b));
    asm("add.rn.f32x2 %0, %1, %2;" : "=l"(s1) : "l"(c), "l"(d));
    asm("add.rn.f32x2 %0, %1, %2;" : "=l"(s0) : "l"(s0), "l"(s1));
    float lo, hi;
    asm("mov.b64 {%0, %1}, %2;" : "=f"(lo), "=f"(hi) : "l"(s0));
    return lo + hi;
}
__device__ __forceinline__ float sigm(float z) {
    return __fdividef(1.0f, 1.0f + __expf(-z));
}
__device__ __forceinline__ void barA() {      // A-group barrier: warps 0-2 only
    asm volatile("bar.sync 1, 96;" ::: "memory");
}

// Full 76-float dot of smem vector (16B-aligned, zero-padded) against 38
// packed-f32x2 register weights. 4 accumulators -> dep chain depth ~10.
__device__ __forceinline__ float dot76(const float* __restrict__ v,
                                       const unsigned long long* __restrict__ w) {
    const ulonglong2* p = (const ulonglong2*)v;
    unsigned long long a0 = 0ull, a1 = 0ull, a2 = 0ull, a3 = 0ull;
#pragma unroll
    for (int i = 0; i < 19; ++i) {
        const ulonglong2 hv = p[i];               // broadcast LDS.128
        if (i & 1) { fma2(a2, w[2 * i], hv.x); fma2(a3, w[2 * i + 1], hv.y); }
        else       { fma2(a0, w[2 * i], hv.x); fma2(a1, w[2 * i + 1], hv.y); }
    }
    return hsum4(a0, a1, a2, a3);
}

// ---------------------------------------------------------------------------
// Kernel 2: decoupled-role recurrence. One batch row per block, 256 blocks,
// 2 blocks/SM. Ring buffers (depth 8) + role lags break the full-block
// lockstep: only the A warps barrier per step (96-thread bar.sync 1);
// B trails A by 4 steps, C trails B by 4; one __syncthreads per 4-step epoch.
//   warps 0-2: A  h_t     = sigm(W2 . h_{t-1} + xp_t + b2)   -> hring[t&7]
//   warps 3-5: B  o_t     = sigm(Wo . h_t + bo)              -> oring[t&7]
//   warps 6-9: C  out_t   = Wfc . o_t + bfc                  -> gmem
// Slot-disjointness per epoch (te=4e): A writes te..te+3, B reads te-4..te-1,
// B writes te-4..te-1, C reads te-8..te-5 — all disjoint mod 8.
// ---------------------------------------------------------------------------
__global__ __launch_bounds__(NTHR, 2) void rnn_kernel(
    const int*   __restrict__ X,
    const float* __restrict__ W2, const float* __restrict__ b2,
    const float* __restrict__ Wo, const float* __restrict__ bo,
    const float* __restrict__ Wfc, const float* __restrict__ bfc,
    float* __restrict__ out)
{
    __shared__ __align__(16) float hring[RING][KP_];
    __shared__ __align__(16) float oring[RING][KP_];
    __shared__ int toks[S_];

    const int tid = threadIdx.x;
    const int row = blockIdx.x;

    const bool isA = tid < 96;
    const bool isB = (tid >= 96) && (tid < 192);
    const int  j   = isA ? tid : (isB ? tid - 96 : tid - 192);
    const int  nrows = (isA || isB) ? H_ : L_;
    const bool vj  = j < nrows;

    // ---- init rings + tokens ----
    for (int i = tid; i < RING * KP_; i += NTHR) {
        ((float*)hring)[i] = 0.f; ((float*)oring)[i] = 0.f;
    }
    for (int i = tid; i < S_; i += NTHR) toks[i] = X[row * S_ + i];

    // ---- weights: one row per thread, packed k-pairs (38 x u64) ----
    const float* Wbase = isA ? W2 : (isB ? Wo : Wfc);
    unsigned long long w[38];
#pragma unroll
    for (int c = 0; c < 38; ++c) {
        const int k = 2 * c;
        float lo = 0.f, hi = 0.f;
        if (vj) {
            if (k     < H_) lo = Wbase[j * H_ + k];
            if (k + 1 < H_) hi = Wbase[j * H_ + k + 1];
        }
        w[c] = pack2(lo, hi);
    }
    float br = 0.f;
    if (vj) br = isA ? b2[j] : (isB ? bo[j] : bfc[j]);
    float* outp = out + ((size_t)row * S_) * L_ + j;   // used by C

    __syncthreads();

    // xp for epoch 0 (steps 0..3)
    float xq[4];
    if (isA && vj) {
#pragma unroll
        for (int s = 0; s < 4; ++s)
            xq[s] = g_embp[(size_t)toks[s] * HP_ + j];
    }

    for (int e = 0; e < EPOCHS; ++e) {
        const int te = 4 * e;

        if (isA) {
            // 4 recurrence steps; only A warps barrier between them.
#pragma unroll
            for (int s = 0; s < 4; ++s) {
                const int tA = te + s;
                if (vj && tA < S_) {
                    const float z = dot76(hring[(tA + RING - 1) & (RING - 1)], w)
                                    + xq[s] + br;
                    hring[tA & (RING - 1)][j] = sigm(z);
                }
                // prefetch next epoch's xp for this substep (overlaps chain)
                if (vj) {
                    const int tn = tA + 4;
                    xq[s] = (tn < S_) ? g_embp[(size_t)toks[tn] * HP_ + j] : 0.f;
                }
                barA();
            }
        } else if (isB) {
            // 4 trailing o-steps, no internal barriers (inputs stable this epoch)
#pragma unroll
            for (int s = 0; s < 4; ++s) {
                const int tB = te + s - 4;
                if (vj && tB >= 0 && tB < S_) {
                    const float z = dot76(hring[tB & (RING - 1)], w) + br;
                    oring[tB & (RING - 1)][j] = sigm(z);
                }
            }
        } else {
            // 4 trailing fc outputs, no internal barriers
#pragma unroll
            for (int s = 0; s < 4; ++s) {
                const int tC = te + s - 8;
                if (tC >= 0 && tC < S_) {
                    const float z = dot76(oring[tC & (RING - 1)], w) + br;
                    outp[(size_t)tC * L_] = z;
                }
            }
        }
        __syncthreads();   // publish A->B (h) and B->C (o) for next epoch
    }
}

// ---------------------------------------------------------------------------
extern "C" void kernel_launch(void* const* d_in, const int* in_sizes, int n_in,
                              void* d_out, int out_size) {
    const int*   X   = (const int*)d_in[0];
    const float* emb = (const float*)d_in[1];
    const float* W1  = (const float*)d_in[2];
    const float* b1  = (const float*)d_in[3];
    const float* W2  = (const float*)d_in[4];
    const float* b2  = (const float*)d_in[5];
    const float* Wo  = (const float*)d_in[6];
    const float* bo  = (const float*)d_in[7];
    const float* Wfc = (const float*)d_in[8];
    const float* bfc = (const float*)d_in[9];
    float* out = (float*)d_out;

    embp_kernel<<<V_ / 64, 256>>>(emb, W1, b1);
    rnn_kernel<<<B_, NTHR>>>(X, W2, b2, Wo, bo, Wfc, bfc, out);
}